// round 2
// baseline (speedup 1.0000x reference)
#include <cuda_runtime.h>
#include <math.h>

#define NB 8
#define CC 3
#define HH 512
#define WW 512
#define HY 256
#define WY 256
#define GG 5
#define MM 3
#define LUTN 256

// ---------------- device globals (scratch + precomputed params) ----------------
__device__ float  g_y[NB*CC*HY*WY];        // downsampled pyramid level (6.3 MB)
__device__ float  g_gw[7];                 // 1D gaussian
__device__ float  g_we[3];                 // even-row upsample taps (x2 folded: sqrt of the 2D x4)
__device__ float  g_wo[4];                 // odd-row upsample taps  (x2 folded)
__device__ float4 g_P0[GG];                // mu0,mu1,mu2, (-0.5*logdet + log_softmax(pi))
__device__ float4 g_P1[GG];                // -0.5*Sinv00, -0.5*Sinv11, -0.5*Sinv22, -Sinv01
__device__ float4 g_P2[GG];                // -Sinv02, -Sinv12, 0, 0
__device__ float4 g_lut[GG*(LUTN+1)];      // membership softmax LUT: (m0,m1,m2,0) vs resp

__device__ __forceinline__ double softplus_d(double x){
    if (x > 30.0) return x;
    return log1p(exp(x));
}

// ---------------- setup: tiny per-launch parameter precompute ----------------
__global__ void setup_kernel(const float* __restrict__ mu,
                             const float* __restrict__ L_raw,
                             const float* __restrict__ pi,
                             const float* __restrict__ mf_c,
                             const float* __restrict__ mf_sL,
                             const float* __restrict__ mf_sR)
{
    int t = threadIdx.x;

    // normalized 1D gaussian (double)
    double gw[7];
    {
        double s = 0.0;
        for (int k = 0; k < 7; k++){
            double r = (double)(k - 3);
            gw[k] = exp(-r*r/(2.0*0.9*0.9));
            s += gw[k];
        }
        for (int k = 0; k < 7; k++) gw[k] /= s;
    }

    if (t == 0){
        for (int k = 0; k < 7; k++) g_gw[k] = (float)gw[k];
        // The 2D transposed-conv kernel is 4*(g outer g). Fold sqrt(4)=2 into EACH 1D stage.
        g_we[0]=(float)(2.0*gw[1]); g_we[1]=(float)(2.0*gw[3]); g_we[2]=(float)(2.0*gw[5]);
        g_wo[0]=(float)(2.0*gw[0]); g_wo[1]=(float)(2.0*gw[2]);
        g_wo[2]=(float)(2.0*gw[4]); g_wo[3]=(float)(2.0*gw[6]);

        // log_softmax(pi)
        double pmx = -1e300;
        for (int g = 0; g < GG; g++) pmx = fmax(pmx, (double)pi[g]);
        double ps = 0.0;
        for (int g = 0; g < GG; g++) ps += exp((double)pi[g] - pmx);
        double lse = pmx + log(ps);

        for (int g = 0; g < GG; g++){
            double L[3][3];
            for (int i = 0; i < 3; i++)
                for (int j = 0; j < 3; j++)
                    L[i][j] = (j < i) ? (double)L_raw[(g*3+i)*3+j] : 0.0;
            for (int i = 0; i < 3; i++)
                L[i][i] = softplus_d(softplus_d((double)L_raw[(g*3+i)*3+i]) + 1e-4) + 1e-4;

            double S[3][3];
            for (int i = 0; i < 3; i++)
                for (int j = 0; j < 3; j++){
                    double acc = 0.0;
                    for (int k = 0; k < 3; k++) acc += L[i][k]*L[j][k];
                    S[i][j] = acc + (i==j ? 1e-4 : 0.0);
                }

            double detS = S[0][0]*(S[1][1]*S[2][2]-S[1][2]*S[1][2])
                        - S[0][1]*(S[0][1]*S[2][2]-S[1][2]*S[0][2])
                        + S[0][2]*(S[0][1]*S[1][2]-S[1][1]*S[0][2]);

            double A00=S[0][0]+1e-3, A11=S[1][1]+1e-3, A22=S[2][2]+1e-3;
            double A01=S[0][1],      A02=S[0][2],      A12=S[1][2];
            double detA = A00*(A11*A22-A12*A12) - A01*(A01*A22-A12*A02) + A02*(A01*A12-A11*A02);
            double id = 1.0/detA;
            double i00 = (A11*A22-A12*A12)*id;
            double i11 = (A00*A22-A02*A02)*id;
            double i22 = (A00*A11-A01*A01)*id;
            double i01 = (A02*A12-A01*A22)*id;
            double i02 = (A01*A12-A02*A11)*id;
            double i12 = (A01*A02-A00*A12)*id;

            g_P0[g] = make_float4(mu[g*3+0], mu[g*3+1], mu[g*3+2],
                                  (float)(-0.5*log(detS) + ((double)pi[g]-lse)));
            g_P1[g] = make_float4((float)(-0.5*i00), (float)(-0.5*i11),
                                  (float)(-0.5*i22), (float)(-i01));
            g_P2[g] = make_float4((float)(-i02), (float)(-i12), 0.f, 0.f);
        }
    }

    // membership LUT: full 3-way softmax vs resp (C1-smooth -> linear interp safe)
    if (t <= LUTN){
        double rv = (double)t / (double)LUTN;
        for (int g = 0; g < GG; g++){
            double z[MM];
            for (int m = 0; m < MM; m++){
                double c  = (double)mf_c [g*MM+m];
                double sl = softplus_d((double)mf_sL[g*MM+m]) + 1e-12;
                double sr = softplus_d((double)mf_sR[g*MM+m]) + 1e-12;
                double sg = (rv < c) ? sl : sr;
                double d  = (rv - c)/sg;
                z[m] = -0.5*d*d;
            }
            double mz = fmax(z[0], fmax(z[1], z[2]));
            double e0 = exp(z[0]-mz), e1 = exp(z[1]-mz), e2 = exp(z[2]-mz);
            double is = 1.0/(e0+e1+e2);
            g_lut[g*(LUTN+1)+t] = make_float4((float)(e0*is), (float)(e1*is), (float)(e2*is), 0.f);
        }
    }
}

// ---------------- kernel 1: reflect-pad + separable 7x7 blur + stride-2 downsample ----------------
__global__ __launch_bounds__(256)
void down_kernel(const float* __restrict__ x)
{
    __shared__ float xs[37][136];   // x tile (37 rows x 133 used cols)
    __shared__ float tmp[16][136];  // vertically blurred, stride-2 rows

    int t  = threadIdx.x;
    int j0 = blockIdx.x * 64;       // y col tile origin
    int i0 = blockIdx.y * 16;       // y row tile origin
    int nc = blockIdx.z;            // n*3 + c

    const float* xb = x + (size_t)nc * (HH*WW);

    float w[7];
    #pragma unroll
    for (int k = 0; k < 7; k++) w[k] = g_gw[k];

    int r0 = 2*i0 - 3, c0 = 2*j0 - 3;
    for (int idx = t; idx < 37*133; idx += 256){
        int ri = idx / 133, ci = idx - ri*133;
        int rr = r0 + ri; rr = (rr < 0) ? -rr : ((rr > 511) ? 1022 - rr : rr);
        int cc = c0 + ci; cc = (cc < 0) ? -cc : ((cc > 511) ? 1022 - cc : cc);
        xs[ri][ci] = xb[rr*WW + cc];
    }
    __syncthreads();

    for (int idx = t; idx < 16*133; idx += 256){
        int r = idx / 133, q = idx - r*133;
        float s = 0.f;
        #pragma unroll
        for (int a = 0; a < 7; a++) s += w[a]*xs[2*r+a][q];
        tmp[r][q] = s;
    }
    __syncthreads();

    float* yb = g_y + (size_t)nc * (HY*WY);
    int jl = t & 63;
    int rb = t >> 6;
    #pragma unroll
    for (int rr = 0; rr < 4; rr++){
        int r = rb*4 + rr;
        float s = 0.f;
        #pragma unroll
        for (int b = 0; b < 7; b++) s += w[b]*tmp[r][2*jl+b];
        yb[(i0+r)*WY + j0 + jl] = s;
    }
}

// ---------------- kernel 2: fused upsample + GMM responsibilities + membership + coalesced store ----------------
__global__ __launch_bounds__(256)
void up_gmm_kernel(float* __restrict__ out)
{
    __shared__ float  yt[3][19][20];       // y tile (3 ch, zero-padded at image border)
    __shared__ float  rs[3][19][32];       // horizontal upsample row-sums per output col
    __shared__ float  stage[256*15];       // output staging (stride-15: conflict-free)
    __shared__ float4 lutS[GG*(LUTN+1)];
    __shared__ float4 sP0[GG], sP1[GG], sP2[GG];
    __shared__ float  swe[3], swo[4];

    int tx = threadIdx.x, ty = threadIdx.y;
    int t  = ty*32 + tx;
    int v0 = blockIdx.x * 32;
    int u0 = blockIdx.y * 32;
    int n  = blockIdx.z;

    for (int idx = t; idx < GG*(LUTN+1); idx += 256) lutS[idx] = g_lut[idx];
    if (t < GG){ sP0[t] = g_P0[t]; sP1[t] = g_P1[t]; sP2[t] = g_P2[t]; }
    if (t < 3) swe[t] = g_we[t];
    if (t < 4) swo[t] = g_wo[t];

    int iy0 = u0/2 - 1, jy0 = v0/2 - 1;
    for (int idx = t; idx < 3*19*19; idx += 256){
        int c   = idx / 361;
        int rem = idx - c*361;
        int li  = rem / 19;
        int lj  = rem - li*19;
        int gi = iy0 + li, gj = jy0 + lj;
        float v = 0.f;
        if ((unsigned)gi < 256u && (unsigned)gj < 256u)
            v = g_y[((n*3 + c) << 16) + (gi << 8) + gj];
        yt[c][li][lj] = v;
    }
    __syncthreads();

    // horizontal composite-upsample row sums: rs[c][i][vl]
    for (int idx = t; idx < 3*19*32; idx += 256){
        int c   = idx / 608;
        int rem = idx - c*608;
        int li  = rem >> 5;
        int vl  = rem & 31;
        float s;
        if (vl & 1){
            int lj = (vl - 1) >> 1;
            s = swo[0]*yt[c][li][lj]   + swo[1]*yt[c][li][lj+1]
              + swo[2]*yt[c][li][lj+2] + swo[3]*yt[c][li][lj+3];
        } else {
            int lj = vl >> 1;
            s = swe[0]*yt[c][li][lj] + swe[1]*yt[c][li][lj+1] + swe[2]*yt[c][li][lj+2];
        }
        rs[c][li][vl] = s;
    }
    __syncthreads();

    for (int slab = 0; slab < 4; slab++){
        int ul = slab*8 + ty;   // local output row; parity warp-uniform (ty fixed)

        float xr0, xr1, xr2;
        if (ul & 1){
            int li0 = (ul - 1) >> 1;
            xr0 = swo[0]*rs[0][li0][tx] + swo[1]*rs[0][li0+1][tx] + swo[2]*rs[0][li0+2][tx] + swo[3]*rs[0][li0+3][tx];
            xr1 = swo[0]*rs[1][li0][tx] + swo[1]*rs[1][li0+1][tx] + swo[2]*rs[1][li0+2][tx] + swo[3]*rs[1][li0+3][tx];
            xr2 = swo[0]*rs[2][li0][tx] + swo[1]*rs[2][li0+1][tx] + swo[2]*rs[2][li0+2][tx] + swo[3]*rs[2][li0+3][tx];
        } else {
            int li0 = ul >> 1;
            xr0 = swe[0]*rs[0][li0][tx] + swe[1]*rs[0][li0+1][tx] + swe[2]*rs[0][li0+2][tx];
            xr1 = swe[0]*rs[1][li0][tx] + swe[1]*rs[1][li0+1][tx] + swe[2]*rs[1][li0+2][tx];
            xr2 = swe[0]*rs[2][li0][tx] + swe[1]*rs[2][li0+1][tx] + swe[2]*rs[2][li0+2][tx];
        }

        // GMM logits (quadratic form with -0.5 folded) + softmax over G
        float lg[GG];
        float mx = -3.4e38f;
        #pragma unroll
        for (int g = 0; g < GG; g++){
            float4 p0 = sP0[g], p1 = sP1[g], p2 = sP2[g];
            float d0 = xr0 - p0.x, d1 = xr1 - p0.y, d2 = xr2 - p0.z;
            float q = p0.w
                    + p1.x*d0*d0 + p1.y*d1*d1 + p1.z*d2*d2
                    + p1.w*d0*d1 + p2.x*d0*d2 + p2.y*d1*d2;
            lg[g] = q;
            mx = fmaxf(mx, q);
        }
        float e[GG], ssum = 0.f;
        #pragma unroll
        for (int g = 0; g < GG; g++){ e[g] = __expf(lg[g] - mx); ssum += e[g]; }
        float inv = __fdividef(1.0f, ssum);

        // membership via LUT interpolation, staged to smem
        float* st = &stage[t*15];
        #pragma unroll
        for (int g = 0; g < GG; g++){
            float r  = e[g]*inv;                  // resp in [0,1]
            float tf = r * (float)LUTN;
            int   i0 = (int)tf; if (i0 > LUTN-1) i0 = LUTN-1;
            float f  = tf - (float)i0;
            float4 a = lutS[g*(LUTN+1) + i0];
            float4 b = lutS[g*(LUTN+1) + i0 + 1];
            st[g*3+0] = a.x + f*(b.x - a.x);
            st[g*3+1] = a.y + f*(b.y - a.y);
            st[g*3+2] = a.z + f*(b.z - a.z);
        }
        __syncthreads();

        // coalesced float4 flush: 8 rows x 480 floats = 960 float4
        for (int idx = t; idx < 960; idx += 256){
            int r  = idx / 120;
            int c4 = idx - r*120;
            int u  = u0 + slab*8 + r;
            size_t base = (((size_t)(n*512 + u))*512 + v0)*15 + (size_t)c4*4;
            *(float4*)&out[base] = *(const float4*)&stage[r*480 + c4*4];
        }
        __syncthreads();
    }
}

// ---------------- launch ----------------
extern "C" void kernel_launch(void* const* d_in, const int* in_sizes, int n_in,
                              void* d_out, int out_size)
{
    (void)in_sizes; (void)n_in; (void)out_size;
    const float* x     = (const float*)d_in[0];
    const float* mu    = (const float*)d_in[1];
    const float* L_raw = (const float*)d_in[2];
    const float* pi    = (const float*)d_in[3];
    const float* mf_c  = (const float*)d_in[4];
    const float* mf_sL = (const float*)d_in[5];
    const float* mf_sR = (const float*)d_in[6];
    float* out = (float*)d_out;

    setup_kernel<<<1, 288>>>(mu, L_raw, pi, mf_c, mf_sL, mf_sR);
    down_kernel<<<dim3(WY/64, HY/16, NB*CC), 256>>>(x);
    up_gmm_kernel<<<dim3(WW/32, HH/32, NB), dim3(32, 8)>>>(out);
}

// round 3
// speedup vs baseline: 1.3301x; 1.3301x over previous
#include <cuda_runtime.h>
#include <math.h>

#define NB 8
#define CC 3
#define HH 512
#define WW 512
#define HY 256
#define WY 256
#define GG 5
#define MM 3
#define LUTN 256

// ---------------- device globals (scratch + precomputed params) ----------------
__device__ float  g_y[NB*CC*HY*WY];        // downsampled pyramid level (6.3 MB)
__device__ float  g_gw[7];                 // 1D gaussian
__device__ float  g_we[3];                 // even-row upsample taps (x2 folded: sqrt of the 2D x4)
__device__ float  g_wo[4];                 // odd-row upsample taps  (x2 folded)
__device__ float4 g_P0[GG];                // mu0,mu1,mu2, (-0.5*logdet + log_softmax(pi))
__device__ float4 g_P1[GG];                // -0.5*Sinv00, -0.5*Sinv11, -0.5*Sinv22, -Sinv01
__device__ float4 g_P2[GG];                // -Sinv02, -Sinv12, 0, 0
__device__ float4 g_lut[GG*(LUTN+1)];      // membership softmax LUT: (m0,m1,m2,0) vs resp

__device__ __forceinline__ double softplus_d(double x){
    if (x > 30.0) return x;
    return log1p(exp(x));
}
__device__ __forceinline__ float softplus_f(float x){
    if (x > 20.f) return x;
    return log1pf(__expf(x));
}

// ---------------- setup: tiny per-launch parameter precompute (fp32 hot path) ----------------
__global__ void setup_kernel(const float* __restrict__ mu,
                             const float* __restrict__ L_raw,
                             const float* __restrict__ pi,
                             const float* __restrict__ mf_c,
                             const float* __restrict__ mf_sL,
                             const float* __restrict__ mf_sR)
{
    int t = threadIdx.x;

    // normalized 1D gaussian (double; only 7 exps per thread -> cheap)
    double gw[7];
    {
        double s = 0.0;
        for (int k = 0; k < 7; k++){
            double r = (double)(k - 3);
            gw[k] = exp(-r*r/(2.0*0.9*0.9));
            s += gw[k];
        }
        for (int k = 0; k < 7; k++) gw[k] /= s;
    }

    if (t == 0){
        for (int k = 0; k < 7; k++) g_gw[k] = (float)gw[k];
        // 2D transposed-conv kernel is 4*(g outer g): fold sqrt(4)=2 into EACH 1D stage.
        g_we[0]=(float)(2.0*gw[1]); g_we[1]=(float)(2.0*gw[3]); g_we[2]=(float)(2.0*gw[5]);
        g_wo[0]=(float)(2.0*gw[0]); g_wo[1]=(float)(2.0*gw[2]);
        g_wo[2]=(float)(2.0*gw[4]); g_wo[3]=(float)(2.0*gw[6]);
    }

    // per-Gaussian parameter block: parallel over g (5 threads), double for safety
    if (t < GG){
        int g = t;
        // log_softmax(pi)
        double pmx = -1e300;
        for (int q = 0; q < GG; q++) pmx = fmax(pmx, (double)pi[q]);
        double ps = 0.0;
        for (int q = 0; q < GG; q++) ps += exp((double)pi[q] - pmx);
        double lse = pmx + log(ps);

        double L[3][3];
        for (int i = 0; i < 3; i++)
            for (int j = 0; j < 3; j++)
                L[i][j] = (j < i) ? (double)L_raw[(g*3+i)*3+j] : 0.0;
        for (int i = 0; i < 3; i++)
            L[i][i] = softplus_d(softplus_d((double)L_raw[(g*3+i)*3+i]) + 1e-4) + 1e-4;

        double S[3][3];
        for (int i = 0; i < 3; i++)
            for (int j = 0; j < 3; j++){
                double acc = 0.0;
                for (int k = 0; k < 3; k++) acc += L[i][k]*L[j][k];
                S[i][j] = acc + (i==j ? 1e-4 : 0.0);
            }

        double detS = S[0][0]*(S[1][1]*S[2][2]-S[1][2]*S[1][2])
                    - S[0][1]*(S[0][1]*S[2][2]-S[1][2]*S[0][2])
                    + S[0][2]*(S[0][1]*S[1][2]-S[1][1]*S[0][2]);

        double A00=S[0][0]+1e-3, A11=S[1][1]+1e-3, A22=S[2][2]+1e-3;
        double A01=S[0][1],      A02=S[0][2],      A12=S[1][2];
        double detA = A00*(A11*A22-A12*A12) - A01*(A01*A22-A12*A02) + A02*(A01*A12-A11*A02);
        double id = 1.0/detA;
        double i00 = (A11*A22-A12*A12)*id;
        double i11 = (A00*A22-A02*A02)*id;
        double i22 = (A00*A11-A01*A01)*id;
        double i01 = (A02*A12-A01*A22)*id;
        double i02 = (A01*A12-A02*A11)*id;
        double i12 = (A01*A02-A00*A12)*id;

        g_P0[g] = make_float4(mu[g*3+0], mu[g*3+1], mu[g*3+2],
                              (float)(-0.5*log(detS) + ((double)pi[g]-lse)));
        g_P1[g] = make_float4((float)(-0.5*i00), (float)(-0.5*i11),
                              (float)(-0.5*i22), (float)(-i01));
        g_P2[g] = make_float4((float)(-i02), (float)(-i12), 0.f, 0.f);
    }

    // membership LUT in fp32 (MUFU): C1-smooth in resp -> linear interp safe
    if (t <= LUTN){
        float rv = (float)t / (float)LUTN;
        #pragma unroll
        for (int g = 0; g < GG; g++){
            float z[MM];
            #pragma unroll
            for (int m = 0; m < MM; m++){
                float c  = mf_c [g*MM+m];
                float sl = softplus_f(mf_sL[g*MM+m]) + 1e-12f;
                float sr = softplus_f(mf_sR[g*MM+m]) + 1e-12f;
                float sg = (rv < c) ? sl : sr;
                float d  = (rv - c)/sg;
                z[m] = -0.5f*d*d;
            }
            float mz = fmaxf(z[0], fmaxf(z[1], z[2]));
            float e0 = __expf(z[0]-mz), e1 = __expf(z[1]-mz), e2 = __expf(z[2]-mz);
            float is = __fdividef(1.f, e0+e1+e2);
            g_lut[g*(LUTN+1)+t] = make_float4(e0*is, e1*is, e2*is, 0.f);
        }
    }
}

// ---------------- kernel 1: reflect-pad + separable 7x7 blur + stride-2 downsample ----------------
__global__ __launch_bounds__(256)
void down_kernel(const float* __restrict__ x)
{
    __shared__ float xs[37][136];   // x tile (37 rows x 133 used cols)
    __shared__ float tmp[16][136];  // vertically blurred, stride-2 rows

    int t  = threadIdx.x;
    int j0 = blockIdx.x * 64;       // y col tile origin
    int i0 = blockIdx.y * 16;       // y row tile origin
    int nc = blockIdx.z;            // n*3 + c

    const float* xb = x + (size_t)nc * (HH*WW);

    float w[7];
    #pragma unroll
    for (int k = 0; k < 7; k++) w[k] = g_gw[k];

    int r0 = 2*i0 - 3, c0 = 2*j0 - 3;
    for (int idx = t; idx < 37*133; idx += 256){
        int ri = idx / 133, ci = idx - ri*133;
        int rr = r0 + ri; rr = (rr < 0) ? -rr : ((rr > 511) ? 1022 - rr : rr);
        int cc = c0 + ci; cc = (cc < 0) ? -cc : ((cc > 511) ? 1022 - cc : cc);
        xs[ri][ci] = xb[rr*WW + cc];
    }
    __syncthreads();

    for (int idx = t; idx < 16*133; idx += 256){
        int r = idx / 133, q = idx - r*133;
        float s = 0.f;
        #pragma unroll
        for (int a = 0; a < 7; a++) s += w[a]*xs[2*r+a][q];
        tmp[r][q] = s;
    }
    __syncthreads();

    float* yb = g_y + (size_t)nc * (HY*WY);
    int jl = t & 63;
    int rb = t >> 6;
    #pragma unroll
    for (int rr = 0; rr < 4; rr++){
        int r = rb*4 + rr;
        float s = 0.f;
        #pragma unroll
        for (int b = 0; b < 7; b++) s += w[b]*tmp[r][2*jl+b];
        yb[(i0+r)*WY + j0 + jl] = s;
    }
}

// ---------------- kernel 2: fused upsample + GMM responsibilities + membership + coalesced store ----------------
__global__ __launch_bounds__(256)
void up_gmm_kernel(float* __restrict__ out)
{
    __shared__ float  yt[3][19][20];       // y tile (3 ch, zero-padded at image border)
    __shared__ float  rs[3][19][32];       // horizontal upsample row-sums per output col
    __shared__ float  stage[256*15];       // output staging (stride-15: conflict-free)
    __shared__ float4 lutS[GG*(LUTN+1)];
    __shared__ float4 sP0[GG], sP1[GG], sP2[GG];
    __shared__ float  swe[3], swo[4];

    int tx = threadIdx.x, ty = threadIdx.y;
    int t  = ty*32 + tx;
    int v0 = blockIdx.x * 32;
    int u0 = blockIdx.y * 32;
    int n  = blockIdx.z;

    for (int idx = t; idx < GG*(LUTN+1); idx += 256) lutS[idx] = g_lut[idx];
    if (t < GG){ sP0[t] = g_P0[t]; sP1[t] = g_P1[t]; sP2[t] = g_P2[t]; }
    if (t < 3) swe[t] = g_we[t];
    if (t < 4) swo[t] = g_wo[t];

    int iy0 = u0/2 - 1, jy0 = v0/2 - 1;
    for (int idx = t; idx < 3*19*19; idx += 256){
        int c   = idx / 361;
        int rem = idx - c*361;
        int li  = rem / 19;
        int lj  = rem - li*19;
        int gi = iy0 + li, gj = jy0 + lj;
        float v = 0.f;
        if ((unsigned)gi < 256u && (unsigned)gj < 256u)
            v = g_y[((n*3 + c) << 16) + (gi << 8) + gj];
        yt[c][li][lj] = v;
    }
    __syncthreads();

    // horizontal composite-upsample row sums: rs[c][i][vl]
    for (int idx = t; idx < 3*19*32; idx += 256){
        int c   = idx / 608;
        int rem = idx - c*608;
        int li  = rem >> 5;
        int vl  = rem & 31;
        float s;
        if (vl & 1){
            int lj = (vl - 1) >> 1;
            s = swo[0]*yt[c][li][lj]   + swo[1]*yt[c][li][lj+1]
              + swo[2]*yt[c][li][lj+2] + swo[3]*yt[c][li][lj+3];
        } else {
            int lj = vl >> 1;
            s = swe[0]*yt[c][li][lj] + swe[1]*yt[c][li][lj+1] + swe[2]*yt[c][li][lj+2];
        }
        rs[c][li][vl] = s;
    }
    __syncthreads();

    for (int slab = 0; slab < 4; slab++){
        int ul = slab*8 + ty;   // local output row; parity warp-uniform (ty fixed)

        float xr0, xr1, xr2;
        if (ul & 1){
            int li0 = (ul - 1) >> 1;
            xr0 = swo[0]*rs[0][li0][tx] + swo[1]*rs[0][li0+1][tx] + swo[2]*rs[0][li0+2][tx] + swo[3]*rs[0][li0+3][tx];
            xr1 = swo[0]*rs[1][li0][tx] + swo[1]*rs[1][li0+1][tx] + swo[2]*rs[1][li0+2][tx] + swo[3]*rs[1][li0+3][tx];
            xr2 = swo[0]*rs[2][li0][tx] + swo[1]*rs[2][li0+1][tx] + swo[2]*rs[2][li0+2][tx] + swo[3]*rs[2][li0+3][tx];
        } else {
            int li0 = ul >> 1;
            xr0 = swe[0]*rs[0][li0][tx] + swe[1]*rs[0][li0+1][tx] + swe[2]*rs[0][li0+2][tx];
            xr1 = swe[0]*rs[1][li0][tx] + swe[1]*rs[1][li0+1][tx] + swe[2]*rs[1][li0+2][tx];
            xr2 = swe[0]*rs[2][li0][tx] + swe[1]*rs[2][li0+1][tx] + swe[2]*rs[2][li0+2][tx];
        }

        // GMM logits (quadratic form with -0.5 folded) + softmax over G
        float lg[GG];
        float mx = -3.4e38f;
        #pragma unroll
        for (int g = 0; g < GG; g++){
            float4 p0 = sP0[g], p1 = sP1[g], p2 = sP2[g];
            float d0 = xr0 - p0.x, d1 = xr1 - p0.y, d2 = xr2 - p0.z;
            float q = p0.w
                    + p1.x*d0*d0 + p1.y*d1*d1 + p1.z*d2*d2
                    + p1.w*d0*d1 + p2.x*d0*d2 + p2.y*d1*d2;
            lg[g] = q;
            mx = fmaxf(mx, q);
        }
        float e[GG], ssum = 0.f;
        #pragma unroll
        for (int g = 0; g < GG; g++){ e[g] = __expf(lg[g] - mx); ssum += e[g]; }
        float inv = __fdividef(1.0f, ssum);

        // membership via LUT interpolation, staged to smem
        float* st = &stage[t*15];
        #pragma unroll
        for (int g = 0; g < GG; g++){
            float r  = e[g]*inv;                  // resp in [0,1]
            float tf = r * (float)LUTN;
            int   i0 = (int)tf; if (i0 > LUTN-1) i0 = LUTN-1;
            float f  = tf - (float)i0;
            float4 a = lutS[g*(LUTN+1) + i0];
            float4 b = lutS[g*(LUTN+1) + i0 + 1];
            st[g*3+0] = a.x + f*(b.x - a.x);
            st[g*3+1] = a.y + f*(b.y - a.y);
            st[g*3+2] = a.z + f*(b.z - a.z);
        }
        __syncthreads();

        // coalesced streaming float4 flush: 8 rows x 480 floats = 960 float4
        for (int idx = t; idx < 960; idx += 256){
            int r  = idx / 120;
            int c4 = idx - r*120;
            int u  = u0 + slab*8 + r;
            size_t base = (((size_t)(n*512 + u))*512 + v0)*15 + (size_t)c4*4;
            __stcs((float4*)&out[base], *(const float4*)&stage[r*480 + c4*4]);
        }
        __syncthreads();
    }
}

// ---------------- launch ----------------
extern "C" void kernel_launch(void* const* d_in, const int* in_sizes, int n_in,
                              void* d_out, int out_size)
{
    (void)in_sizes; (void)n_in; (void)out_size;
    const float* x     = (const float*)d_in[0];
    const float* mu    = (const float*)d_in[1];
    const float* L_raw = (const float*)d_in[2];
    const float* pi    = (const float*)d_in[3];
    const float* mf_c  = (const float*)d_in[4];
    const float* mf_sL = (const float*)d_in[5];
    const float* mf_sR = (const float*)d_in[6];
    float* out = (float*)d_out;

    setup_kernel<<<1, 288>>>(mu, L_raw, pi, mf_c, mf_sL, mf_sR);
    down_kernel<<<dim3(WY/64, HY/16, NB*CC), 256>>>(x);
    up_gmm_kernel<<<dim3(WW/32, HH/32, NB), dim3(32, 8)>>>(out);
}

// round 4
// speedup vs baseline: 1.4857x; 1.1170x over previous
#include <cuda_runtime.h>
#include <math.h>

#define NB 8
#define CC 3
#define HH 512
#define WW 512
#define HY 256
#define WY 256
#define GG 5
#define MM 3
#define LUTN 64

// ---------------- device globals (scratch + precomputed params) ----------------
__device__ float  g_y[NB*CC*HY*WY];        // downsampled pyramid level (6.3 MB)
__device__ float  g_we[3];                 // even-row upsample taps (x2 folded: sqrt of the 2D x4)
__device__ float  g_wo[4];                 // odd-row upsample taps  (x2 folded)
__device__ float4 g_P0[GG];                // mu0,mu1,mu2, (-0.5*logdet + log_softmax(pi))
__device__ float4 g_P1[GG];                // -0.5*Sinv00, -0.5*Sinv11, -0.5*Sinv22, -Sinv01
__device__ float4 g_P2[GG];                // -Sinv02, -Sinv12, 0, 0
__device__ float4 g_lut[GG*(LUTN+1)];      // membership softmax LUT: (m0,m1,m2,0) vs resp

__device__ __forceinline__ float softplus_f(float x){
    if (x > 20.f) return x;
    return log1pf(__expf(x));
}

// fp32 1D gaussian weights (deterministic, matches reference to ~1ulp fp32)
__device__ __forceinline__ void gauss7(float* gw){
    float s = 0.f;
    #pragma unroll
    for (int k = 0; k < 7; k++){
        float r = (float)(k - 3);
        gw[k] = __expf(-r*r/(2.f*0.9f*0.9f));
        s += gw[k];
    }
    float is = 1.f/s;
    #pragma unroll
    for (int k = 0; k < 7; k++) gw[k] *= is;
}

// ---------------- setup work (runs inside down_kernel's extra z-slice, fp32) ----------------
__device__ void do_setup(const float* __restrict__ mu,
                         const float* __restrict__ L_raw,
                         const float* __restrict__ pi,
                         const float* __restrict__ mf_c,
                         const float* __restrict__ mf_sL,
                         const float* __restrict__ mf_sR,
                         int t)
{
    float gw[7];
    gauss7(gw);

    if (t == 0){
        // 2D transposed-conv kernel is 4*(g outer g): fold sqrt(4)=2 into EACH 1D stage.
        g_we[0]=2.f*gw[1]; g_we[1]=2.f*gw[3]; g_we[2]=2.f*gw[5];
        g_wo[0]=2.f*gw[0]; g_wo[1]=2.f*gw[2]; g_wo[2]=2.f*gw[4]; g_wo[3]=2.f*gw[6];
    }

    // per-Gaussian parameter block: parallel over g (5 threads), fp32
    // (Sigma is well-conditioned: L diag >= softplus(softplus(0)) ~ 0.69)
    if (t < GG){
        int g = t;
        // log_softmax(pi)
        float pmx = -3.4e38f;
        for (int q = 0; q < GG; q++) pmx = fmaxf(pmx, pi[q]);
        float ps = 0.f;
        for (int q = 0; q < GG; q++) ps += __expf(pi[q] - pmx);
        float lse = pmx + logf(ps);

        float L[3][3];
        for (int i = 0; i < 3; i++)
            for (int j = 0; j < 3; j++)
                L[i][j] = (j < i) ? L_raw[(g*3+i)*3+j] : 0.f;
        for (int i = 0; i < 3; i++)
            L[i][i] = softplus_f(softplus_f(L_raw[(g*3+i)*3+i]) + 1e-4f) + 1e-4f;

        float S[3][3];
        for (int i = 0; i < 3; i++)
            for (int j = 0; j < 3; j++){
                float acc = 0.f;
                for (int k = 0; k < 3; k++) acc += L[i][k]*L[j][k];
                S[i][j] = acc + (i==j ? 1e-4f : 0.f);
            }

        float detS = S[0][0]*(S[1][1]*S[2][2]-S[1][2]*S[1][2])
                   - S[0][1]*(S[0][1]*S[2][2]-S[1][2]*S[0][2])
                   + S[0][2]*(S[0][1]*S[1][2]-S[1][1]*S[0][2]);

        float A00=S[0][0]+1e-3f, A11=S[1][1]+1e-3f, A22=S[2][2]+1e-3f;
        float A01=S[0][1],       A02=S[0][2],       A12=S[1][2];
        float detA = A00*(A11*A22-A12*A12) - A01*(A01*A22-A12*A02) + A02*(A01*A12-A11*A02);
        float id = 1.f/detA;
        float i00 = (A11*A22-A12*A12)*id;
        float i11 = (A00*A22-A02*A02)*id;
        float i22 = (A00*A11-A01*A01)*id;
        float i01 = (A02*A12-A01*A22)*id;
        float i02 = (A01*A12-A02*A11)*id;
        float i12 = (A01*A02-A00*A12)*id;

        g_P0[g] = make_float4(mu[g*3+0], mu[g*3+1], mu[g*3+2],
                              -0.5f*logf(detS) + (pi[g]-lse));
        g_P1[g] = make_float4(-0.5f*i00, -0.5f*i11, -0.5f*i22, -i01);
        g_P2[g] = make_float4(-i02, -i12, 0.f, 0.f);
    }

    // membership LUT in fp32: C1-smooth in resp -> linear interp safe (~1e-5 err at 64 bins)
    if (t <= LUTN){
        float rv = (float)t / (float)LUTN;
        #pragma unroll
        for (int g = 0; g < GG; g++){
            float z[MM];
            #pragma unroll
            for (int m = 0; m < MM; m++){
                float c  = mf_c [g*MM+m];
                float sl = softplus_f(mf_sL[g*MM+m]) + 1e-12f;
                float sr = softplus_f(mf_sR[g*MM+m]) + 1e-12f;
                float sg = (rv < c) ? sl : sr;
                float d  = (rv - c)/sg;
                z[m] = -0.5f*d*d;
            }
            float mz = fmaxf(z[0], fmaxf(z[1], z[2]));
            float e0 = __expf(z[0]-mz), e1 = __expf(z[1]-mz), e2 = __expf(z[2]-mz);
            float is = __fdividef(1.f, e0+e1+e2);
            g_lut[g*(LUTN+1)+t] = make_float4(e0*is, e1*is, e2*is, 0.f);
        }
    }
}

// ---------------- kernel 1: reflect-pad blur downsample  (+ setup in extra z-slice) ----------------
__global__ __launch_bounds__(256)
void down_kernel(const float* __restrict__ x,
                 const float* __restrict__ mu,
                 const float* __restrict__ L_raw,
                 const float* __restrict__ pi,
                 const float* __restrict__ mf_c,
                 const float* __restrict__ mf_sL,
                 const float* __restrict__ mf_sR)
{
    __shared__ float xs[37][136];   // x tile (37 rows x 133 used cols)
    __shared__ float tmp[16][136];  // vertically blurred, stride-2 rows

    int t  = threadIdx.x;
    int nc = blockIdx.z;            // n*3 + c  (or NB*CC -> setup slice)

    if (nc == NB*CC){
        if (blockIdx.x == 0 && blockIdx.y == 0)
            do_setup(mu, L_raw, pi, mf_c, mf_sL, mf_sR, t);
        return;
    }

    int j0 = blockIdx.x * 64;       // y col tile origin
    int i0 = blockIdx.y * 16;       // y row tile origin

    const float* xb = x + (size_t)nc * (HH*WW);

    float w[7];
    gauss7(w);

    int r0 = 2*i0 - 3, c0 = 2*j0 - 3;
    for (int idx = t; idx < 37*133; idx += 256){
        int ri = idx / 133, ci = idx - ri*133;
        int rr = r0 + ri; rr = (rr < 0) ? -rr : ((rr > 511) ? 1022 - rr : rr);
        int cc = c0 + ci; cc = (cc < 0) ? -cc : ((cc > 511) ? 1022 - cc : cc);
        xs[ri][ci] = __ldcs(&xb[rr*WW + cc]);
    }
    __syncthreads();

    for (int idx = t; idx < 16*133; idx += 256){
        int r = idx / 133, q = idx - r*133;
        float s = 0.f;
        #pragma unroll
        for (int a = 0; a < 7; a++) s += w[a]*xs[2*r+a][q];
        tmp[r][q] = s;
    }
    __syncthreads();

    float* yb = g_y + (size_t)nc * (HY*WY);
    int jl = t & 63;
    int rb = t >> 6;
    #pragma unroll
    for (int rr = 0; rr < 4; rr++){
        int r = rb*4 + rr;
        float s = 0.f;
        #pragma unroll
        for (int b = 0; b < 7; b++) s += w[b]*tmp[r][2*jl+b];
        yb[(i0+r)*WY + j0 + jl] = s;
    }
}

// ---------------- kernel 2: fused upsample + GMM responsibilities + membership + coalesced store ----------------
__global__ __launch_bounds__(256)
void up_gmm_kernel(float* __restrict__ out)
{
    __shared__ float  yt[3][19][20];       // y tile (3 ch, zero-padded at image border)
    __shared__ float  rs[3][19][32];       // horizontal upsample row-sums per output col
    __shared__ float  stage[256*15];       // output staging (stride-15: conflict-free)
    __shared__ float4 lutS[GG*(LUTN+1)];
    __shared__ float4 sP0[GG], sP1[GG], sP2[GG];
    __shared__ float  swe[3], swo[4];

    int tx = threadIdx.x, ty = threadIdx.y;
    int t  = ty*32 + tx;
    int v0 = blockIdx.x * 32;
    int u0 = blockIdx.y * 32;
    int n  = blockIdx.z;

    for (int idx = t; idx < GG*(LUTN+1); idx += 256) lutS[idx] = g_lut[idx];
    if (t < GG){ sP0[t] = g_P0[t]; sP1[t] = g_P1[t]; sP2[t] = g_P2[t]; }
    if (t < 3) swe[t] = g_we[t];
    if (t < 4) swo[t] = g_wo[t];

    int iy0 = u0/2 - 1, jy0 = v0/2 - 1;
    for (int idx = t; idx < 3*19*19; idx += 256){
        int c   = idx / 361;
        int rem = idx - c*361;
        int li  = rem / 19;
        int lj  = rem - li*19;
        int gi = iy0 + li, gj = jy0 + lj;
        float v = 0.f;
        if ((unsigned)gi < 256u && (unsigned)gj < 256u)
            v = g_y[((n*3 + c) << 16) + (gi << 8) + gj];
        yt[c][li][lj] = v;
    }
    __syncthreads();

    // horizontal composite-upsample row sums: rs[c][i][vl]
    for (int idx = t; idx < 3*19*32; idx += 256){
        int c   = idx / 608;
        int rem = idx - c*608;
        int li  = rem >> 5;
        int vl  = rem & 31;
        float s;
        if (vl & 1){
            int lj = (vl - 1) >> 1;
            s = swo[0]*yt[c][li][lj]   + swo[1]*yt[c][li][lj+1]
              + swo[2]*yt[c][li][lj+2] + swo[3]*yt[c][li][lj+3];
        } else {
            int lj = vl >> 1;
            s = swe[0]*yt[c][li][lj] + swe[1]*yt[c][li][lj+1] + swe[2]*yt[c][li][lj+2];
        }
        rs[c][li][vl] = s;
    }
    __syncthreads();

    for (int slab = 0; slab < 4; slab++){
        int ul = slab*8 + ty;   // local output row; parity warp-uniform (ty fixed)

        float xr0, xr1, xr2;
        if (ul & 1){
            int li0 = (ul - 1) >> 1;
            xr0 = swo[0]*rs[0][li0][tx] + swo[1]*rs[0][li0+1][tx] + swo[2]*rs[0][li0+2][tx] + swo[3]*rs[0][li0+3][tx];
            xr1 = swo[0]*rs[1][li0][tx] + swo[1]*rs[1][li0+1][tx] + swo[2]*rs[1][li0+2][tx] + swo[3]*rs[1][li0+3][tx];
            xr2 = swo[0]*rs[2][li0][tx] + swo[1]*rs[2][li0+1][tx] + swo[2]*rs[2][li0+2][tx] + swo[3]*rs[2][li0+3][tx];
        } else {
            int li0 = ul >> 1;
            xr0 = swe[0]*rs[0][li0][tx] + swe[1]*rs[0][li0+1][tx] + swe[2]*rs[0][li0+2][tx];
            xr1 = swe[0]*rs[1][li0][tx] + swe[1]*rs[1][li0+1][tx] + swe[2]*rs[1][li0+2][tx];
            xr2 = swe[0]*rs[2][li0][tx] + swe[1]*rs[2][li0+1][tx] + swe[2]*rs[2][li0+2][tx];
        }

        // GMM logits (quadratic form with -0.5 folded) + softmax over G
        float lg[GG];
        float mx = -3.4e38f;
        #pragma unroll
        for (int g = 0; g < GG; g++){
            float4 p0 = sP0[g], p1 = sP1[g], p2 = sP2[g];
            float d0 = xr0 - p0.x, d1 = xr1 - p0.y, d2 = xr2 - p0.z;
            float q = p0.w
                    + p1.x*d0*d0 + p1.y*d1*d1 + p1.z*d2*d2
                    + p1.w*d0*d1 + p2.x*d0*d2 + p2.y*d1*d2;
            lg[g] = q;
            mx = fmaxf(mx, q);
        }
        float e[GG], ssum = 0.f;
        #pragma unroll
        for (int g = 0; g < GG; g++){ e[g] = __expf(lg[g] - mx); ssum += e[g]; }
        float inv = __fdividef(1.0f, ssum);

        // membership via LUT interpolation, staged to smem
        float* st = &stage[t*15];
        #pragma unroll
        for (int g = 0; g < GG; g++){
            float r  = e[g]*inv;                  // resp in [0,1]
            float tf = r * (float)LUTN;
            int   i0 = (int)tf; if (i0 > LUTN-1) i0 = LUTN-1;
            float f  = tf - (float)i0;
            float4 a = lutS[g*(LUTN+1) + i0];
            float4 b = lutS[g*(LUTN+1) + i0 + 1];
            st[g*3+0] = a.x + f*(b.x - a.x);
            st[g*3+1] = a.y + f*(b.y - a.y);
            st[g*3+2] = a.z + f*(b.z - a.z);
        }
        __syncthreads();

        // coalesced streaming float4 flush: 8 rows x 480 floats = 960 float4
        for (int idx = t; idx < 960; idx += 256){
            int r  = idx / 120;
            int c4 = idx - r*120;
            int u  = u0 + slab*8 + r;
            size_t base = (((size_t)(n*512 + u))*512 + v0)*15 + (size_t)c4*4;
            __stcs((float4*)&out[base], *(const float4*)&stage[r*480 + c4*4]);
        }
        __syncthreads();
    }
}

// ---------------- launch ----------------
extern "C" void kernel_launch(void* const* d_in, const int* in_sizes, int n_in,
                              void* d_out, int out_size)
{
    (void)in_sizes; (void)n_in; (void)out_size;
    const float* x     = (const float*)d_in[0];
    const float* mu    = (const float*)d_in[1];
    const float* L_raw = (const float*)d_in[2];
    const float* pi    = (const float*)d_in[3];
    const float* mf_c  = (const float*)d_in[4];
    const float* mf_sL = (const float*)d_in[5];
    const float* mf_sR = (const float*)d_in[6];
    float* out = (float*)d_out;

    down_kernel<<<dim3(WY/64, HY/16, NB*CC + 1), 256>>>(x, mu, L_raw, pi, mf_c, mf_sL, mf_sR);
    up_gmm_kernel<<<dim3(WW/32, HH/32, NB), dim3(32, 8)>>>(out);
}

// round 5
// speedup vs baseline: 1.5038x; 1.0122x over previous
#include <cuda_runtime.h>
#include <math.h>

#define NB 8
#define CC 3
#define HH 512
#define WW 512
#define HY 256
#define WY 256
#define GG 5
#define MM 3
#define LUTN 64
#define LOG2E 1.4426950408889634f

// ---------------- device globals (scratch + precomputed params) ----------------
__device__ float  g_y[NB*CC*HY*WY];        // downsampled pyramid level (6.3 MB)
__device__ float  g_we[3];                 // even-row upsample taps (x2 folded: sqrt of the 2D x4)
__device__ float  g_wo[4];                 // odd-row upsample taps  (x2 folded)
__device__ float4 g_P0[GG];                // mu0,mu1,mu2, LOG2E*(-0.5*logdet + log_softmax(pi))
__device__ float4 g_P1[GG];                // LOG2E * {-0.5*Sinv00, -0.5*Sinv11, -0.5*Sinv22, -Sinv01}
__device__ float4 g_P2[GG];                // LOG2E * {-Sinv02, -Sinv12}, 0, 0
__device__ float  g_lut[GG*(LUTN+1)*3];    // membership LUT, stride-3 scalars (bank-conflict-free gather)

__device__ __forceinline__ float softplus_f(float x){
    if (x > 20.f) return x;
    return log1pf(__expf(x));
}
__device__ __forceinline__ float ex2f(float x){
    float y; asm("ex2.approx.ftz.f32 %0, %1;" : "=f"(y) : "f"(x)); return y;
}

// fp32 1D gaussian weights
__device__ __forceinline__ void gauss7(float* gw){
    float s = 0.f;
    #pragma unroll
    for (int k = 0; k < 7; k++){
        float r = (float)(k - 3);
        gw[k] = __expf(-r*r/(2.f*0.9f*0.9f));
        s += gw[k];
    }
    float is = 1.f/s;
    #pragma unroll
    for (int k = 0; k < 7; k++) gw[k] *= is;
}

// ---------------- setup work (runs inside down_kernel's extra z-slice, fp32) ----------------
__device__ void do_setup(const float* __restrict__ mu,
                         const float* __restrict__ L_raw,
                         const float* __restrict__ pi,
                         const float* __restrict__ mf_c,
                         const float* __restrict__ mf_sL,
                         const float* __restrict__ mf_sR,
                         int t)
{
    float gw[7];
    gauss7(gw);

    if (t == 0){
        // 2D transposed-conv kernel is 4*(g outer g): fold sqrt(4)=2 into EACH 1D stage.
        g_we[0]=2.f*gw[1]; g_we[1]=2.f*gw[3]; g_we[2]=2.f*gw[5];
        g_wo[0]=2.f*gw[0]; g_wo[1]=2.f*gw[2]; g_wo[2]=2.f*gw[4]; g_wo[3]=2.f*gw[6];
    }

    // per-Gaussian parameter block: parallel over g, fp32 (Sigma well-conditioned)
    if (t < GG){
        int g = t;
        float pmx = -3.4e38f;
        for (int q = 0; q < GG; q++) pmx = fmaxf(pmx, pi[q]);
        float ps = 0.f;
        for (int q = 0; q < GG; q++) ps += __expf(pi[q] - pmx);
        float lse = pmx + logf(ps);

        float L[3][3];
        for (int i = 0; i < 3; i++)
            for (int j = 0; j < 3; j++)
                L[i][j] = (j < i) ? L_raw[(g*3+i)*3+j] : 0.f;
        for (int i = 0; i < 3; i++)
            L[i][i] = softplus_f(softplus_f(L_raw[(g*3+i)*3+i]) + 1e-4f) + 1e-4f;

        float S[3][3];
        for (int i = 0; i < 3; i++)
            for (int j = 0; j < 3; j++){
                float acc = 0.f;
                for (int k = 0; k < 3; k++) acc += L[i][k]*L[j][k];
                S[i][j] = acc + (i==j ? 1e-4f : 0.f);
            }

        float detS = S[0][0]*(S[1][1]*S[2][2]-S[1][2]*S[1][2])
                   - S[0][1]*(S[0][1]*S[2][2]-S[1][2]*S[0][2])
                   + S[0][2]*(S[0][1]*S[1][2]-S[1][1]*S[0][2]);

        float A00=S[0][0]+1e-3f, A11=S[1][1]+1e-3f, A22=S[2][2]+1e-3f;
        float A01=S[0][1],       A02=S[0][2],       A12=S[1][2];
        float detA = A00*(A11*A22-A12*A12) - A01*(A01*A22-A12*A02) + A02*(A01*A12-A11*A02);
        float id = 1.f/detA;
        float i00 = (A11*A22-A12*A12)*id;
        float i11 = (A00*A22-A02*A02)*id;
        float i22 = (A00*A11-A01*A01)*id;
        float i01 = (A02*A12-A01*A22)*id;
        float i02 = (A01*A12-A02*A11)*id;
        float i12 = (A01*A02-A00*A12)*id;

        // everything that enters the logit is pre-scaled by LOG2E (exp2 domain)
        g_P0[g] = make_float4(mu[g*3+0], mu[g*3+1], mu[g*3+2],
                              LOG2E*(-0.5f*logf(detS) + (pi[g]-lse)));
        g_P1[g] = make_float4(LOG2E*-0.5f*i00, LOG2E*-0.5f*i11, LOG2E*-0.5f*i22, LOG2E*-i01);
        g_P2[g] = make_float4(LOG2E*-i02, LOG2E*-i12, 0.f, 0.f);
    }

    // membership LUT in fp32: stride-3 scalar layout (m0,m1,m2)
    if (t <= LUTN){
        float rv = (float)t / (float)LUTN;
        #pragma unroll
        for (int g = 0; g < GG; g++){
            float z[MM];
            #pragma unroll
            for (int m = 0; m < MM; m++){
                float c  = mf_c [g*MM+m];
                float sl = softplus_f(mf_sL[g*MM+m]) + 1e-12f;
                float sr = softplus_f(mf_sR[g*MM+m]) + 1e-12f;
                float sg = (rv < c) ? sl : sr;
                float d  = (rv - c)/sg;
                z[m] = -0.5f*d*d;
            }
            float mz = fmaxf(z[0], fmaxf(z[1], z[2]));
            float e0 = __expf(z[0]-mz), e1 = __expf(z[1]-mz), e2 = __expf(z[2]-mz);
            float is = __fdividef(1.f, e0+e1+e2);
            float* o = &g_lut[(g*(LUTN+1)+t)*3];
            o[0] = e0*is; o[1] = e1*is; o[2] = e2*is;
        }
    }
}

// ---------------- kernel 1: reflect-pad blur downsample  (+ setup in extra z-slice) ----------------
__global__ __launch_bounds__(256)
void down_kernel(const float* __restrict__ x,
                 const float* __restrict__ mu,
                 const float* __restrict__ L_raw,
                 const float* __restrict__ pi,
                 const float* __restrict__ mf_c,
                 const float* __restrict__ mf_sL,
                 const float* __restrict__ mf_sR)
{
    __shared__ float xs[37][136];   // x tile (37 rows x 133 used cols)
    __shared__ float tmp[16][136];  // vertically blurred, stride-2 rows

    int t  = threadIdx.x;
    int nc = blockIdx.z;            // n*3 + c  (or NB*CC -> setup slice)

    if (nc == NB*CC){
        if (blockIdx.x == 0 && blockIdx.y == 0)
            do_setup(mu, L_raw, pi, mf_c, mf_sL, mf_sR, t);
        return;
    }

    int j0 = blockIdx.x * 64;       // y col tile origin
    int i0 = blockIdx.y * 16;       // y row tile origin

    const float* xb = x + (size_t)nc * (HH*WW);

    float w[7];
    gauss7(w);

    int r0 = 2*i0 - 3, c0 = 2*j0 - 3;
    for (int idx = t; idx < 37*133; idx += 256){
        int ri = idx / 133, ci = idx - ri*133;
        int rr = r0 + ri; rr = (rr < 0) ? -rr : ((rr > 511) ? 1022 - rr : rr);
        int cc = c0 + ci; cc = (cc < 0) ? -cc : ((cc > 511) ? 1022 - cc : cc);
        xs[ri][ci] = __ldcs(&xb[rr*WW + cc]);
    }
    __syncthreads();

    for (int idx = t; idx < 16*133; idx += 256){
        int r = idx / 133, q = idx - r*133;
        float s = 0.f;
        #pragma unroll
        for (int a = 0; a < 7; a++) s += w[a]*xs[2*r+a][q];
        tmp[r][q] = s;
    }
    __syncthreads();

    float* yb = g_y + (size_t)nc * (HY*WY);
    int jl = t & 63;
    int rb = t >> 6;
    #pragma unroll
    for (int rr = 0; rr < 4; rr++){
        int r = rb*4 + rr;
        float s = 0.f;
        #pragma unroll
        for (int b = 0; b < 7; b++) s += w[b]*tmp[r][2*jl+b];
        yb[(i0+r)*WY + j0 + jl] = s;
    }
}

// ---------------- kernel 2: fused upsample + GMM responsibilities + membership + coalesced store ----------------
__global__ __launch_bounds__(256)
void up_gmm_kernel(float* __restrict__ out)
{
    __shared__ float  yt[3][19][20];       // y tile (3 ch, zero-padded at image border)
    __shared__ float  rs[3][19][32];       // horizontal upsample row-sums per output col
    __shared__ float  stage[256*15];       // output staging (stride-15: conflict-free)
    __shared__ float  lutS[GG*(LUTN+1)*3]; // stride-3: gather sweeps all 32 banks
    __shared__ float4 sP0[GG], sP1[GG], sP2[GG];
    __shared__ float  swe[3], swo[4];

    int tx = threadIdx.x, ty = threadIdx.y;
    int t  = ty*32 + tx;
    int v0 = blockIdx.x * 32;
    int u0 = blockIdx.y * 32;
    int n  = blockIdx.z;

    for (int idx = t; idx < GG*(LUTN+1)*3; idx += 256) lutS[idx] = g_lut[idx];
    if (t < GG){ sP0[t] = g_P0[t]; sP1[t] = g_P1[t]; sP2[t] = g_P2[t]; }
    if (t < 3) swe[t] = g_we[t];
    if (t < 4) swo[t] = g_wo[t];

    int iy0 = u0/2 - 1, jy0 = v0/2 - 1;
    for (int idx = t; idx < 3*19*19; idx += 256){
        int c   = idx / 361;
        int rem = idx - c*361;
        int li  = rem / 19;
        int lj  = rem - li*19;
        int gi = iy0 + li, gj = jy0 + lj;
        float v = 0.f;
        if ((unsigned)gi < 256u && (unsigned)gj < 256u)
            v = g_y[((n*3 + c) << 16) + (gi << 8) + gj];
        yt[c][li][lj] = v;
    }
    __syncthreads();

    // horizontal composite-upsample row sums: rs[c][i][vl]
    for (int idx = t; idx < 3*19*32; idx += 256){
        int c   = idx / 608;
        int rem = idx - c*608;
        int li  = rem >> 5;
        int vl  = rem & 31;
        float s;
        if (vl & 1){
            int lj = (vl - 1) >> 1;
            s = swo[0]*yt[c][li][lj]   + swo[1]*yt[c][li][lj+1]
              + swo[2]*yt[c][li][lj+2] + swo[3]*yt[c][li][lj+3];
        } else {
            int lj = vl >> 1;
            s = swe[0]*yt[c][li][lj] + swe[1]*yt[c][li][lj+1] + swe[2]*yt[c][li][lj+2];
        }
        rs[c][li][vl] = s;
    }
    __syncthreads();

    for (int slab = 0; slab < 4; slab++){
        int ul = slab*8 + ty;   // local output row; parity warp-uniform (ty fixed)

        float xr0, xr1, xr2;
        if (ul & 1){
            int li0 = (ul - 1) >> 1;
            xr0 = swo[0]*rs[0][li0][tx] + swo[1]*rs[0][li0+1][tx] + swo[2]*rs[0][li0+2][tx] + swo[3]*rs[0][li0+3][tx];
            xr1 = swo[0]*rs[1][li0][tx] + swo[1]*rs[1][li0+1][tx] + swo[2]*rs[1][li0+2][tx] + swo[3]*rs[1][li0+3][tx];
            xr2 = swo[0]*rs[2][li0][tx] + swo[1]*rs[2][li0+1][tx] + swo[2]*rs[2][li0+2][tx] + swo[3]*rs[2][li0+3][tx];
        } else {
            int li0 = ul >> 1;
            xr0 = swe[0]*rs[0][li0][tx] + swe[1]*rs[0][li0+1][tx] + swe[2]*rs[0][li0+2][tx];
            xr1 = swe[0]*rs[1][li0][tx] + swe[1]*rs[1][li0+1][tx] + swe[2]*rs[1][li0+2][tx];
            xr2 = swe[0]*rs[2][li0][tx] + swe[1]*rs[2][li0+1][tx] + swe[2]*rs[2][li0+2][tx];
        }

        // GMM logits in exp2 domain + softmax over G
        float lg[GG];
        float mx = -3.4e38f;
        #pragma unroll
        for (int g = 0; g < GG; g++){
            float4 p0 = sP0[g], p1 = sP1[g], p2 = sP2[g];
            float d0 = xr0 - p0.x, d1 = xr1 - p0.y, d2 = xr2 - p0.z;
            float q = p0.w
                    + p1.x*d0*d0 + p1.y*d1*d1 + p1.z*d2*d2
                    + p1.w*d0*d1 + p2.x*d0*d2 + p2.y*d1*d2;
            lg[g] = q;
            mx = fmaxf(mx, q);
        }
        float e[GG], ssum = 0.f;
        #pragma unroll
        for (int g = 0; g < GG; g++){ e[g] = ex2f(lg[g] - mx); ssum += e[g]; }
        float inv = __fdividef(1.0f, ssum);

        // membership via LUT interpolation (stride-3 conflict-free gather), staged to smem
        float* st = &stage[t*15];
        #pragma unroll
        for (int g = 0; g < GG; g++){
            float r  = e[g]*inv;                  // resp in [0,1]
            float tf = r * (float)LUTN;
            int   i0 = (int)tf; if (i0 > LUTN-1) i0 = LUTN-1;
            float f  = tf - (float)i0;
            const float* A = &lutS[g*((LUTN+1)*3) + i0*3];
            float a0 = A[0], a1 = A[1], a2 = A[2];
            float b0 = A[3], b1 = A[4], b2 = A[5];
            st[g*3+0] = fmaf(f, b0 - a0, a0);
            st[g*3+1] = fmaf(f, b1 - a1, a1);
            st[g*3+2] = fmaf(f, b2 - a2, a2);
        }
        __syncthreads();

        // coalesced streaming float4 flush: 8 rows x 480 floats = 960 float4
        for (int idx = t; idx < 960; idx += 256){
            int r  = idx / 120;
            int c4 = idx - r*120;
            int u  = u0 + slab*8 + r;
            size_t base = (((size_t)(n*512 + u))*512 + v0)*15 + (size_t)c4*4;
            __stcs((float4*)&out[base], *(const float4*)&stage[r*480 + c4*4]);
        }
        __syncthreads();
    }
}

// ---------------- launch ----------------
extern "C" void kernel_launch(void* const* d_in, const int* in_sizes, int n_in,
                              void* d_out, int out_size)
{
    (void)in_sizes; (void)n_in; (void)out_size;
    const float* x     = (const float*)d_in[0];
    const float* mu    = (const float*)d_in[1];
    const float* L_raw = (const float*)d_in[2];
    const float* pi    = (const float*)d_in[3];
    const float* mf_c  = (const float*)d_in[4];
    const float* mf_sL = (const float*)d_in[5];
    const float* mf_sR = (const float*)d_in[6];
    float* out = (float*)d_out;

    down_kernel<<<dim3(WY/64, HY/16, NB*CC + 1), 256>>>(x, mu, L_raw, pi, mf_c, mf_sL, mf_sR);
    up_gmm_kernel<<<dim3(WW/32, HH/32, NB), dim3(32, 8)>>>(out);
}